// round 1
// baseline (speedup 1.0000x reference)
#include <cuda_runtime.h>
#include <cuda_bf16.h>
#include <math.h>

// Problem constants (hardcoded for this dataset: B=2, H=W=512)
#define B   2
#define H   512
#define W   512
#define HW  (H*W)            // 262144
#define PH  (H+1)            // pooled H = 513
#define PW  (W+1)            // pooled W = 513
#define PHW (PH*PW)          // 263169

// Scratch (static device memory; allocation APIs are forbidden)
__device__ float g_ang[(size_t)B * 8 * HW];       // (B,8,512,512)  16 MB
__device__ float g_pooled[(size_t)B * 8 * PHW];   // (B,8,513,513)  16.8 MB

__device__ __forceinline__ float fsqrt_fast(float x) {
    float r;
    asm("sqrt.approx.f32 %0, %1;" : "=f"(r) : "f"(x));
    return r;
}

// ----------------------------------------------------------------------------
// K1: spatial gradient (central diff /2, replicate pad) -> mag/ori -> 8-bin
//     soft angular histogram. Writes dense ang (only 2 of 8 channels nonzero).
// ----------------------------------------------------------------------------
__global__ __launch_bounds__(256)
void k_ang(const float* __restrict__ x) {
    const int j = blockIdx.x * 32 + threadIdx.x;
    const int i = blockIdx.y * 8  + threadIdx.y;
    const int b = blockIdx.z;

    const float* xb = x + (size_t)b * HW;
    const int jm = max(j - 1, 0),     jp = min(j + 1, W - 1);
    const int im = max(i - 1, 0),     ip = min(i + 1, H - 1);

    const float gx = 0.5f * (xb[i * W + jp] - xb[i * W + jm]);
    const float gy = 0.5f * (xb[ip * W + j] - xb[im * W + j]);

    const float mag = sqrtf(gx * gx + gy * gy + 1e-10f);
    const float TWO_PI = 6.283185307179586f;
    const float ori = atan2f(gy, gx + 1e-10f) + TWO_PI;   // (pi, 3pi]
    const float o   = ori * (8.0f / TWO_PI);              // (4, 12]
    const float bof = floorf(o);
    const float w1  = o - bof;                            // [0,1)
    const int b0 = ((int)bof) & 7;
    const int b1 = (b0 + 1) & 7;
    const float v0 = (1.0f - w1) * mag;
    const float v1 = w1 * mag;

    float* ap = g_ang + (size_t)b * 8 * HW + (size_t)i * W + j;
#pragma unroll
    for (int d = 0; d < 8; d++) {
        float v = (d == b0) ? v0 : ((d == b1) ? v1 : 0.0f);
        ap[(size_t)d * HW] = v;
    }
}

// ----------------------------------------------------------------------------
// K2: 4x4 triangular pooling (separable weights [.25,.75,.75,.25]^2), pad=2,
//     stride 1, zero padding. ang(512x512) -> pooled(513x513) per channel.
// ----------------------------------------------------------------------------
__global__ __launch_bounds__(256)
void k_pool() {
    const int q  = blockIdx.x * 32 + threadIdx.x;   // 0..512
    const int p  = blockIdx.y * 8  + threadIdx.y;   // 0..512
    const int bd = blockIdx.z;                      // 0..15  (b*8+d)
    if (p >= PH || q >= PW) return;

    const float* a = g_ang + (size_t)bd * HW;
    const float wv[4] = {0.25f, 0.75f, 0.75f, 0.25f};

    float acc = 0.0f;
#pragma unroll
    for (int ky = 0; ky < 4; ky++) {
        const int r = p - 2 + ky;
        if (r < 0 || r >= H) continue;
        float rowacc = 0.0f;
#pragma unroll
        for (int kx = 0; kx < 4; kx++) {
            const int c = q - 2 + kx;
            if (c < 0 || c >= W) continue;
            rowacc = fmaf(wv[kx], a[(size_t)r * W + c], rowacc);
        }
        acc = fmaf(wv[ky], rowacc, acc);
    }
    g_pooled[(size_t)bd * PHW + (size_t)p * PW + q] = acc;
}

// ----------------------------------------------------------------------------
// K3: fused neigh2channels gather + collapsed normalization chain.
//     out[b, d*16+y*4+x, i, j] = f( pooled[b,d,i-1+y,j-1+x] ) with
//     f(v) = sqrt( min(v, 0.2*||v||2) / S + 1e-10 ),  S = sum min(v, 0.2*||v||2)
//     (the L2 / clip / L2 / L1 chain algebraically collapses to this).
// ----------------------------------------------------------------------------
#define TX 32
#define TY 8

__global__ __launch_bounds__(256)
void k_final(float* __restrict__ out) {
    __shared__ float tile[8][TY + 3][TX + 3];   // [d][11][35] = 12320 B

    const int b  = blockIdx.z;
    const int j0 = blockIdx.x * TX;
    const int i0 = blockIdx.y * TY;
    const int tx = threadIdx.x, ty = threadIdx.y;
    const int tid = ty * TX + tx;

    // Load pooled tile: rows i0-1 .. i0+TY+1, cols j0-1 .. j0+TX+1, 8 channels.
    // Out-of-range pooled coords (reshape-conv zero padding) -> 0.
    const float* pb = g_pooled + (size_t)b * 8 * PHW;
    const int NLOAD = 8 * (TY + 3) * (TX + 3);
    for (int idx = tid; idx < NLOAD; idx += TX * TY) {
        const int d   = idx / ((TY + 3) * (TX + 3));
        const int rem = idx % ((TY + 3) * (TX + 3));
        const int r = rem / (TX + 3);
        const int c = rem % (TX + 3);
        const int pp = i0 - 1 + r;
        const int qq = j0 - 1 + c;
        float v = 0.0f;
        if (pp >= 0 && pp < PH && qq >= 0 && qq < PW)
            v = pb[(size_t)d * PHW + (size_t)pp * PW + qq];
        tile[d][r][c] = v;
    }
    __syncthreads();

    const int i = i0 + ty;
    const int j = j0 + tx;

    // Pass 1: sum of squares over the 128-vector
    float sumsq = 0.0f;
#pragma unroll
    for (int d = 0; d < 8; d++)
#pragma unroll
        for (int y = 0; y < 4; y++)
#pragma unroll
            for (int xk = 0; xk < 4; xk++) {
                const float v = tile[d][ty + y][tx + xk];
                sumsq = fmaf(v, v, sumsq);
            }

    const float t = 0.2f * sqrtf(sumsq);   // clip threshold in value space

    // Pass 2: clipped L1 sum
    float S = 0.0f;
#pragma unroll
    for (int d = 0; d < 8; d++)
#pragma unroll
        for (int y = 0; y < 4; y++)
#pragma unroll
            for (int xk = 0; xk < 4; xk++)
                S += fminf(tile[d][ty + y][tx + xk], t);

    const float invS = 1.0f / fmaxf(S, 1e-20f);

    // Pass 3: write 128 channels. For fixed channel c the warp writes 32
    // consecutive j -> fully coalesced 128B STG per channel.
    float* ob = out + (size_t)b * 128 * HW + (size_t)i * W + j;
#pragma unroll
    for (int d = 0; d < 8; d++)
#pragma unroll
        for (int y = 0; y < 4; y++)
#pragma unroll
            for (int xk = 0; xk < 4; xk++) {
                const int c = d * 16 + y * 4 + xk;
                const float v = fminf(tile[d][ty + y][tx + xk], t);
                ob[(size_t)c * HW] = fsqrt_fast(fmaf(v, invS, 1e-10f));
            }
}

// ----------------------------------------------------------------------------
extern "C" void kernel_launch(void* const* d_in, const int* in_sizes, int n_in,
                              void* d_out, int out_size) {
    const float* x = (const float*)d_in[0];
    float* out = (float*)d_out;

    dim3 blk(32, 8);
    dim3 g1(W / 32, H / 8, B);                       // (16, 64, 2)
    dim3 g2((PW + 31) / 32, (PH + 7) / 8, B * 8);    // (17, 65, 16)
    dim3 g3(W / TX, H / TY, B);                      // (16, 64, 2)

    k_ang<<<g1, blk>>>(x);
    k_pool<<<g2, blk>>>();
    k_final<<<g3, blk>>>(out);
}